// round 2
// baseline (speedup 1.0000x reference)
#include <cuda_runtime.h>
#include <cstdint>

// CorticalSheet fixed-degree SpMM:
//   out[n, b] = sum_k values[n, k] * x[indices[n, k], b] + bias[n]
// N = 1e6, K = 32, B = 8.
//
// Scheme: quarter-warp per neuron (8 lanes = 8 output columns), 4 neurons/warp.
// Per synapse the 8 lanes of a group read one 32B row -> exactly 1 L1 wavefront
// per gather (hardware floor). Round-2 change: two phases of 16 gathers in
// flight (was 4) so ~512 outstanding loads chip-wide hide the ~250cyc L2-hit
// latency; occupancy is deliberately traded for MLP.

static constexpr int K_SYN = 32;
static constexpr int B_COL = 8;

__global__ __launch_bounds__(256)
void cortical_spmm_kernel(const float* __restrict__ x,
                          const float* __restrict__ values,
                          const float* __restrict__ bias,
                          const int*   __restrict__ indices,
                          float* __restrict__ out,
                          int N) {
    const int tid   = blockIdx.x * blockDim.x + threadIdx.x;
    const int warp  = tid >> 5;
    const int lane  = threadIdx.x & 31;
    const int b     = lane & 7;        // output column owned by this lane
    const int gbase = lane & 24;       // first lane of this 8-lane group

    const long n = (long)warp * 4 + (lane >> 3);   // neuron for this group
    const bool active = (n < N);

    // Preload this group's 32 indices + 32 values, 4 per lane (chunk = b&7? no:
    // chunk id = this lane's column index b). Warp covers 512B contiguous.
    int4   idx4 = make_int4(0, 0, 0, 0);
    float4 val4 = make_float4(0.f, 0.f, 0.f, 0.f);
    float  bi   = 0.f;
    if (active) {
        const size_t base = (size_t)n * K_SYN + (size_t)b * 4;
        idx4 = *reinterpret_cast<const int4*>(indices + base);
        val4 = *reinterpret_cast<const float4*>(values + base);
        bi   = __ldg(bias + n);
    }

    const float* __restrict__ xb = x + b;

    float a0 = 0.f, a1 = 0.f, a2 = 0.f, a3 = 0.f;

    // Two halves; each half keeps 16 independent gathers in flight.
    #pragma unroll
    for (int h = 0; h < 2; ++h) {
        float g[16];
        float v[16];

        #pragma unroll
        for (int c = 0; c < 4; ++c) {
            const int src = gbase + h * 4 + c;  // lane holding this int4 chunk
            const int i0 = __shfl_sync(0xffffffffu, idx4.x, src);
            const int i1 = __shfl_sync(0xffffffffu, idx4.y, src);
            const int i2 = __shfl_sync(0xffffffffu, idx4.z, src);
            const int i3 = __shfl_sync(0xffffffffu, idx4.w, src);
            // Issue the 4 gathers for this chunk immediately; FMAs deferred.
            g[c * 4 + 0] = __ldg(xb + (size_t)i0 * B_COL);
            g[c * 4 + 1] = __ldg(xb + (size_t)i1 * B_COL);
            g[c * 4 + 2] = __ldg(xb + (size_t)i2 * B_COL);
            g[c * 4 + 3] = __ldg(xb + (size_t)i3 * B_COL);
        }

        #pragma unroll
        for (int c = 0; c < 4; ++c) {
            const int src = gbase + h * 4 + c;
            v[c * 4 + 0] = __shfl_sync(0xffffffffu, val4.x, src);
            v[c * 4 + 1] = __shfl_sync(0xffffffffu, val4.y, src);
            v[c * 4 + 2] = __shfl_sync(0xffffffffu, val4.z, src);
            v[c * 4 + 3] = __shfl_sync(0xffffffffu, val4.w, src);
        }

        #pragma unroll
        for (int c = 0; c < 4; ++c) {
            a0 = fmaf(v[c * 4 + 0], g[c * 4 + 0], a0);
            a1 = fmaf(v[c * 4 + 1], g[c * 4 + 1], a1);
            a2 = fmaf(v[c * 4 + 2], g[c * 4 + 2], a2);
            a3 = fmaf(v[c * 4 + 3], g[c * 4 + 3], a3);
        }
    }

    if (active) {
        const float acc = (a0 + a1) + (a2 + a3);
        out[(size_t)n * B_COL + b] = acc + bi;
    }
}

extern "C" void kernel_launch(void* const* d_in, const int* in_sizes, int n_in,
                              void* d_out, int out_size) {
    const float* x       = (const float*)d_in[0];
    const float* values  = (const float*)d_in[1];
    const float* bias    = (const float*)d_in[2];
    const int*   indices = (const int*)d_in[3];
    float* out = (float*)d_out;

    const int N = in_sizes[2];            // bias has one element per neuron

    // 4 neurons per warp, 8 warps per block -> 32 neurons per 256-thread block.
    const int neurons_per_block = 32;
    const int grid = (N + neurons_per_block - 1) / neurons_per_block;

    cortical_spmm_kernel<<<grid, 256>>>(x, values, bias, indices, out, N);
}